// round 13
// baseline (speedup 1.0000x reference)
#include <cuda_runtime.h>
#include <cstdint>
#include <cstddef>

#define NN 16384
#define GG 64

// ------------------------- device scratch (static) -------------------------
__device__ float  g_XYa[NN * 256];   // [x_in | adj@x_in], ld 256
__device__ float  g_XYb[NN * 256];   // [x1   | adj@x1  ], ld 256
__device__ float  g_XR [NN * 128];   // relu(FC) output, reused per layer
__device__ double g_part[128 * 256];
__device__ float  g_inf[NN];
__device__ float  g_ovr[NN];
__device__ unsigned char g_mask[NN];
__device__ int    g_maskMode;
__device__ float  g_bv[64];
__device__ int    g_bi[64];

// ------------------------- helpers -------------------------
__device__ __forceinline__ float tf32r(float v) {
    uint32_t r; asm("cvt.rna.tf32.f32 %0, %1;" : "=r"(r) : "f"(v));
    return __uint_as_float(r);
}
__device__ __forceinline__ void mma8(float c[4],
                                     uint32_t a0, uint32_t a1, uint32_t a2, uint32_t a3,
                                     uint32_t b0, uint32_t b1) {
    asm volatile(
        "mma.sync.aligned.m16n8k8.row.col.f32.tf32.tf32.f32 "
        "{%0,%1,%2,%3},{%4,%5,%6,%7},{%8,%9},{%0,%1,%2,%3};"
        : "+f"(c[0]), "+f"(c[1]), "+f"(c[2]), "+f"(c[3])
        : "r"(a0), "r"(a1), "r"(a2), "r"(a3), "r"(b0), "r"(b1));
}

// ------------------------- mask dtype detection -------------------------
__global__ void detectMaskK(const void* m) {
    const int*   mi = (const int*)m;
    const float* mf = (const float*)m;
    __shared__ int bad_i32, bad_f32, one_i32, one_f32;
    if (threadIdx.x == 0) { bad_i32 = 0; bad_f32 = 0; one_i32 = 0; one_f32 = 0; }
    __syncthreads();
    for (int i = threadIdx.x; i < 4096; i += blockDim.x) {
        int v = mi[i];
        if (v != 0 && v != 1) atomicOr(&bad_i32, 1);
        if (v == 1) atomicOr(&one_i32, 1);
        float f = mf[i];
        if (!(f == 0.0f || f == 1.0f)) atomicOr(&bad_f32, 1);
        if (f == 1.0f) atomicOr(&one_f32, 1);
    }
    __syncthreads();
    if (threadIdx.x == 0) {
        int mode;
        if (!bad_i32 && one_i32) mode = 0;
        else if (!bad_f32 && one_f32) mode = 1;
        else mode = 2;
        g_maskMode = mode;
    }
}

__global__ void convMaskK(const void* m) {
    int i = blockIdx.x * blockDim.x + threadIdx.x;
    if (i >= NN) return;
    int mode = g_maskMode;
    bool b;
    if (mode == 0)      b = ((const int*)m)[i] != 0;
    else if (mode == 1) b = ((const float*)m)[i] != 0.0f;
    else                b = ((const unsigned char*)m)[i] != 0;
    g_mask[i] = b ? 1 : 0;
}

// ------------------------- copy x_in into XYa[:,0:128] -------------------------
__global__ void copyXinK(const float* __restrict__ xin, float* __restrict__ XYa) {
    int i = blockIdx.x * blockDim.x + threadIdx.x;
    if (i >= NN * 32) return;
    int row = i >> 5, q = i & 31;
    ((float4*)XYa)[(size_t)row * 64 + q] = ((const float4*)xin)[i];
}

// ------------------------- tf32x3 mma.sync GEMM, staged pre-split, wide LDS ----------
// C[M x 128] = A[M x K] @ B[K x 128], fp32 in/out, tf32 3-product emulation.
// CTA: 128m x 128n tile, BK=32, 512 threads (16 warps, each 32m x 32n).
// Split ONCE at staging (hi = cvt.rna, lo = raw residual), stored so that the
// inner loop is pure LDS + MMA:
//   A: hi plane + lo plane, stride 40, pair-permuted -> LDS.64 frag loads
//   B: interleaved quads [hi_k, hi_k+4, lo_k, lo_k+4], stride 80 -> LDS.128
// Inner loop per kk8: 8 LDS.64 + 4 LDS.128 + 24 MMA (zero split ALU).
// Values & accumulation order identical to round 9 -> identical numerics.
// Smem: 2 stages x (Ah 5120 + Al 5120 + Bq 10240 floats) = 163840 B dynamic.
template <int MODE>
__global__ void __launch_bounds__(512, 1) mmaGemmK(
    const float* __restrict__ A, int lda,
    const float* __restrict__ B, int ldb,
    float* __restrict__ C, int ldc,
    int K, const float* __restrict__ bias)
{
    extern __shared__ float sm[];   // [2][20480]

    const int t    = threadIdx.x;
    const int lane = t & 31;
    const int w    = t >> 5;
    const int mg   = w & 3;     // 4 m-groups of 32 rows
    const int ng   = w >> 2;    // 4 n-groups of 32 cols
    const int quad = lane >> 2;
    const int tid4 = lane & 3;
    const int m0   = blockIdx.x * 128;

    // staging mappings
    const int ar  = t >> 2;          // A row 0..127
    const int akb = (t & 3) * 8;     // A k-chunk base (0,8,16,24)
    const int bkr = t & 31;          // B k-row 0..31
    const int bnb = (t >> 5) * 8;    // B n-chunk base (16 warps x 8 = 128)

    const float* Ag = A + (size_t)(m0 + ar) * lda + akb;
    const float* Bg = B + (size_t)bkr * ldb + bnb;

    // permuted column for B: bijection of k (0..31); pair pos = bcol>>1, sub = bcol&1
    const int bcol = ((bkr >> 3) << 3) | (((bkr & 3) << 1) | ((bkr & 7) >> 2));
    const int bpp4 = (bcol >> 1) * 4 + (bcol & 1);   // offset within row quads

    float acc[2][4][4];
#pragma unroll
    for (int i = 0; i < 2; ++i)
#pragma unroll
        for (int j = 0; j < 4; ++j)
#pragma unroll
            for (int e = 0; e < 4; ++e) acc[i][j][e] = 0.0f;

    float4 apre[2], bpre[2];
#define LDGS(K0) do { \
        apre[0] = *(const float4*)(Ag + (K0)); \
        apre[1] = *(const float4*)(Ag + (K0) + 4); \
        bpre[0] = *(const float4*)(Bg + (size_t)(K0) * ldb); \
        bpre[1] = *(const float4*)(Bg + (size_t)(K0) * ldb + 4); \
    } while (0)

#define STST(BUF) do { \
        float* Ahd = sm + (BUF) * 20480; \
        float* Ald = Ahd + 5120; \
        float* Bqd = Ahd + 10240; \
        float4 u = apre[0], v = apre[1]; \
        float hx0 = tf32r(u.x), hx1 = tf32r(v.x); \
        float hy0 = tf32r(u.y), hy1 = tf32r(v.y); \
        float hz0 = tf32r(u.z), hz1 = tf32r(v.z); \
        float hw0 = tf32r(u.w), hw1 = tf32r(v.w); \
        float4 ph0 = {hx0, hx1, hy0, hy1}; \
        float4 ph1 = {hz0, hz1, hw0, hw1}; \
        float4 pl0 = {u.x - hx0, v.x - hx1, u.y - hy0, v.y - hy1}; \
        float4 pl1 = {u.z - hz0, v.z - hz1, u.w - hw0, v.w - hw1}; \
        *(float4*)(Ahd + ar * 40 + akb)     = ph0; \
        *(float4*)(Ahd + ar * 40 + akb + 4) = ph1; \
        *(float4*)(Ald + ar * 40 + akb)     = pl0; \
        *(float4*)(Ald + ar * 40 + akb + 4) = pl1; \
        _Pragma("unroll") \
        for (int jj = 0; jj < 2; ++jj) { \
            float4 bv = bpre[jj]; \
            float bh0 = tf32r(bv.x), bh1 = tf32r(bv.y); \
            float bh2 = tf32r(bv.z), bh3 = tf32r(bv.w); \
            int n0 = bnb + jj * 4; \
            Bqd[(n0 + 0) * 80 + bpp4]     = bh0; \
            Bqd[(n0 + 0) * 80 + bpp4 + 2] = bv.x - bh0; \
            Bqd[(n0 + 1) * 80 + bpp4]     = bh1; \
            Bqd[(n0 + 1) * 80 + bpp4 + 2] = bv.y - bh1; \
            Bqd[(n0 + 2) * 80 + bpp4]     = bh2; \
            Bqd[(n0 + 2) * 80 + bpp4 + 2] = bv.z - bh2; \
            Bqd[(n0 + 3) * 80 + bpp4]     = bh3; \
            Bqd[(n0 + 3) * 80 + bpp4 + 2] = bv.w - bh3; \
        } \
    } while (0)

    LDGS(0);
    STST(0);
    __syncthreads();

    const int nT = K >> 5;
    for (int kt = 0; kt < nT; ++kt) {
        const int cur = kt & 1;
        const float* Ahc = sm + cur * 20480;
        const float* Alc = Ahc + 5120;
        const float* Bqc = Ahc + 10240;

        if (kt + 1 < nT) LDGS((kt + 1) << 5);

#pragma unroll
        for (int kk8 = 0; kk8 < 4; ++kk8) {
            const int kp = kk8 * 8 + 2 * tid4;
            uint32_t ah[2][4], al[2][4];
#pragma unroll
            for (int i = 0; i < 2; ++i) {
                int row0 = mg * 32 + i * 16 + quad;
                float2 ph = *(const float2*)(Ahc + row0 * 40 + kp);
                float2 qh = *(const float2*)(Ahc + (row0 + 8) * 40 + kp);
                float2 pl = *(const float2*)(Alc + row0 * 40 + kp);
                float2 ql = *(const float2*)(Alc + (row0 + 8) * 40 + kp);
                ah[i][0] = __float_as_uint(ph.x);
                ah[i][1] = __float_as_uint(qh.x);
                ah[i][2] = __float_as_uint(ph.y);
                ah[i][3] = __float_as_uint(qh.y);
                al[i][0] = __float_as_uint(pl.x);
                al[i][1] = __float_as_uint(ql.x);
                al[i][2] = __float_as_uint(pl.y);
                al[i][3] = __float_as_uint(ql.y);
            }
#pragma unroll
            for (int j = 0; j < 4; ++j) {
                int n = ng * 32 + j * 8 + quad;
                float4 bq = *(const float4*)(Bqc + n * 80 + (kk8 * 4 + tid4) * 4);
                uint32_t bh0 = __float_as_uint(bq.x);
                uint32_t bh1 = __float_as_uint(bq.y);
                uint32_t bl0 = __float_as_uint(bq.z);
                uint32_t bl1 = __float_as_uint(bq.w);
#pragma unroll
                for (int i = 0; i < 2; ++i) {
                    mma8(acc[i][j], ah[i][0], ah[i][1], ah[i][2], ah[i][3], bh0, bh1);
                    mma8(acc[i][j], ah[i][0], ah[i][1], ah[i][2], ah[i][3], bl0, bl1);
                    mma8(acc[i][j], al[i][0], al[i][1], al[i][2], al[i][3], bh0, bh1);
                }
            }
        }

        if (kt + 1 < nT) STST(cur ^ 1);
        __syncthreads();
    }
#undef LDGS
#undef STST

    // epilogue
#pragma unroll
    for (int i = 0; i < 2; ++i) {
        int r0 = m0 + mg * 32 + i * 16 + quad;
#pragma unroll
        for (int j = 0; j < 4; ++j) {
            int c0 = ng * 32 + j * 8 + 2 * tid4;
            float v0 = acc[i][j][0], v1 = acc[i][j][1];
            float v2 = acc[i][j][2], v3 = acc[i][j][3];
            if (MODE == 1) {
                float bb0 = bias[c0], bb1 = bias[c0 + 1];
                v0 = fmaxf(v0 + bb0, 0.0f); v1 = fmaxf(v1 + bb1, 0.0f);
                v2 = fmaxf(v2 + bb0, 0.0f); v3 = fmaxf(v3 + bb1, 0.0f);
            }
            float2 p0 = {v0, v1}, p1 = {v2, v3};
            *(float2*)(C + (size_t)r0 * ldc + c0)       = p0;
            *(float2*)(C + (size_t)(r0 + 8) * ldc + c0) = p1;
        }
    }
}

// ------------------------- column stats (deterministic partials) -------------------------
__global__ void statsK(const float* __restrict__ X, double* __restrict__ part) {
    int c  = threadIdx.x;
    int r0 = blockIdx.x * 128;
    double s = 0.0, q = 0.0;
    for (int r = 0; r < 128; ++r) {
        double v = (double)X[(size_t)(r0 + r) * 128 + c];
        s += v; q += v * v;
    }
    part[blockIdx.x * 256 + c]       = s;
    part[blockIdx.x * 256 + 128 + c] = q;
}

// ------------------------- BN1 + mask -> x1, h1 -> infset -------------------------
__global__ void bn1K(const float* __restrict__ XR, const double* __restrict__ part,
                     const float* __restrict__ g, const float* __restrict__ be,
                     float* __restrict__ X1, float* __restrict__ dout, int out_size) {
    __shared__ float scale[128], shift[128];
    int c = threadIdx.x;
    double s = 0.0, q = 0.0;
    for (int b = 0; b < 128; ++b) { s += part[b * 256 + c]; q += part[b * 256 + 128 + c]; }
    double mu  = s * (1.0 / 16384.0);
    double var = q * (1.0 / 16384.0) - mu * mu; if (var < 0.0) var = 0.0;
    float sc = g[c] * (float)(1.0 / sqrt(var + 1e-5));
    scale[c] = sc;
    shift[c] = be[c] - (float)mu * sc;
    __syncthreads();

    int row = blockIdx.x * 128 + c;
    float sel = g_mask[row] ? 0.0f : 1.0f;
    const float4* xr = (const float4*)(XR + (size_t)row * 128);
    float4* x1 = (float4*)(X1 + (size_t)row * 256);
    float h = 0.0f;
    for (int qd = 0; qd < 32; ++qd) {
        float4 v = xr[qd];
        float4 rr;
        rr.x = sel * (v.x * scale[4 * qd + 0] + shift[4 * qd + 0]);
        rr.y = sel * (v.y * scale[4 * qd + 1] + shift[4 * qd + 1]);
        rr.z = sel * (v.z * scale[4 * qd + 2] + shift[4 * qd + 2]);
        rr.w = sel * (v.w * scale[4 * qd + 3] + shift[4 * qd + 3]);
        h += rr.x + rr.y + rr.z + rr.w;
        x1[qd] = rr;
    }
    float inf = (h <= 0.0f) ? 1.0f : 0.0f;
    g_inf[row] = inf;
    if (64 + row < out_size) dout[64 + row] = inf;
}

// ------------------------- BN2 + mask -> x2 (in place) -------------------------
__global__ void bn2K(float* __restrict__ XR, const double* __restrict__ part,
                     const float* __restrict__ g, const float* __restrict__ be) {
    __shared__ float scale[128], shift[128];
    int c = threadIdx.x;
    double s = 0.0, q = 0.0;
    for (int b = 0; b < 128; ++b) { s += part[b * 256 + c]; q += part[b * 256 + 128 + c]; }
    double mu  = s * (1.0 / 16384.0);
    double var = q * (1.0 / 16384.0) - mu * mu; if (var < 0.0) var = 0.0;
    float sc = g[c] * (float)(1.0 / sqrt(var + 1e-5));
    scale[c] = sc;
    shift[c] = be[c] - (float)mu * sc;
    __syncthreads();

    int row = blockIdx.x * 128 + c;
    float sel = g_mask[row] ? 0.0f : 1.0f;
    float4* xr = (float4*)(XR + (size_t)row * 128);
    for (int qd = 0; qd < 32; ++qd) {
        float4 v = xr[qd];
        float4 rr;
        rr.x = sel * (v.x * scale[4 * qd + 0] + shift[4 * qd + 0]);
        rr.y = sel * (v.y * scale[4 * qd + 1] + shift[4 * qd + 1]);
        rr.z = sel * (v.z * scale[4 * qd + 2] + shift[4 * qd + 2]);
        rr.w = sel * (v.w * scale[4 * qd + 3] + shift[4 * qd + 3]);
        xr[qd] = rr;
    }
}

// ------------------------- per-segment sum + final FC -------------------------
__device__ __forceinline__ int lowerBound(const int* a, int n, int key) {
    int lo = 0, hi = n;
    while (lo < hi) { int mid = (lo + hi) >> 1; if (a[mid] < key) lo = mid + 1; else hi = mid; }
    return lo;
}

__global__ void segOutK(const float* __restrict__ xin, const float* __restrict__ x1,
                        const float* __restrict__ x2, const int* __restrict__ idx,
                        const float* __restrict__ W4, const float* __restrict__ b4,
                        float* __restrict__ dout, int out_size) {
    int g = blockIdx.x, t = threadIdx.x;
    __shared__ float wgt[384];
    __shared__ float red[128];
    wgt[t] = W4[t]; wgt[128 + t] = W4[128 + t]; wgt[256 + t] = W4[256 + t];
    __syncthreads();
    int lo = lowerBound(idx, NN, g);
    int hi = lowerBound(idx, NN, g + 1);
    float acc = 0.0f;
    for (int r = lo; r < hi; ++r) {
        acc += xin[(size_t)r * 128 + t] * wgt[t]
             + x1 [(size_t)r * 256 + t] * wgt[128 + t]
             + x2 [(size_t)r * 128 + t] * wgt[256 + t];
    }
    red[t] = acc;
    __syncthreads();
    for (int s2 = 64; s2 > 0; s2 >>= 1) {
        if (t < s2) red[t] += red[t + s2];
        __syncthreads();
    }
    if (t == 0 && g < out_size) dout[g] = fmaxf(red[0] + b4[0], 0.0f);
}

// ------------------------- ovr = pos @ infset -------------------------
__global__ void ovrK(const float* __restrict__ pos) {
    int row  = blockIdx.x * 8 + (threadIdx.x >> 5);
    int lane = threadIdx.x & 31;
    const float4* p = (const float4*)(pos + (size_t)row * NN);
    const float4* f = (const float4*)g_inf;
    float a = 0.0f;
    for (int j = lane; j < NN / 4; j += 32) {
        float4 pv = p[j]; float4 iv = f[j];
        a += pv.x * iv.x + pv.y * iv.y + pv.z * iv.z + pv.w * iv.w;
    }
#pragma unroll
    for (int o = 16; o > 0; o >>= 1) a += __shfl_down_sync(0xffffffffu, a, o);
    if (lane == 0) g_ovr[row] = a;
}

__global__ void seedK(const int* __restrict__ seed, int nseed) {
    int t = threadIdx.x;
    if (t < nseed) {
        int s = seed[t];
        if (s >= 0 && s < NN) g_ovr[s] = __int_as_float(0xff800000);
    }
}

// ------------------------- argmax -------------------------
__global__ void amax1K() {
    __shared__ float sv[256]; __shared__ int si[256];
    int t = threadIdx.x;
    int i = blockIdx.x * 256 + t;
    sv[t] = g_ovr[i]; si[t] = i;
    __syncthreads();
    for (int s = 128; s > 0; s >>= 1) {
        if (t < s) {
            if (sv[t + s] > sv[t] || (sv[t + s] == sv[t] && si[t + s] < si[t])) {
                sv[t] = sv[t + s]; si[t] = si[t + s];
            }
        }
        __syncthreads();
    }
    if (t == 0) { g_bv[blockIdx.x] = sv[0]; g_bi[blockIdx.x] = si[0]; }
}

__global__ void amax2K(float* __restrict__ dout, int out_size) {
    __shared__ float sv[64]; __shared__ int si[64];
    int t = threadIdx.x;
    sv[t] = g_bv[t]; si[t] = g_bi[t];
    __syncthreads();
    for (int s = 32; s > 0; s >>= 1) {
        if (t < s) {
            if (sv[t + s] > sv[t] || (sv[t + s] == sv[t] && si[t + s] < si[t])) {
                sv[t] = sv[t + s]; si[t] = si[t + s];
            }
        }
        __syncthreads();
    }
    if (t == 0) {
        if (64 + NN < out_size) dout[64 + NN] = (float)si[0];
    }
}

// ------------------------- launch -------------------------
extern "C" void kernel_launch(void* const* d_in, const int* in_sizes, int n_in,
                              void* d_out, int out_size) {
    const float* adj  = (const float*)d_in[0];
    const float* xin  = (const float*)d_in[1];
    const void*  mask =               d_in[2];
    const float* pos  = (const float*)d_in[3];
    const int*   idx  = (const int*)  d_in[4];
    const int*   seed = (const int*)  d_in[5];
    const float* W1  = (const float*)d_in[7];
    const float* b1  = (const float*)d_in[8];
    const float* W2  = (const float*)d_in[9];
    const float* b2  = (const float*)d_in[10];
    const float* W4  = (const float*)d_in[11];
    const float* b4  = (const float*)d_in[12];
    const float* g1  = (const float*)d_in[13];
    const float* be1 = (const float*)d_in[14];
    const float* g2  = (const float*)d_in[15];
    const float* be2 = (const float*)d_in[16];
    float* out = (float*)d_out;
    int nseed = in_sizes[5];

    float  *XYa, *XYb, *XR;
    double *part;
    cudaGetSymbolAddress((void**)&XYa,  g_XYa);
    cudaGetSymbolAddress((void**)&XYb,  g_XYb);
    cudaGetSymbolAddress((void**)&XR,   g_XR);
    cudaGetSymbolAddress((void**)&part, g_part);

    const int SMZ = 2 * 20480 * 4;  // 163840 B dynamic smem
    cudaFuncSetAttribute(mmaGemmK<0>, cudaFuncAttributeMaxDynamicSharedMemorySize, SMZ);
    cudaFuncSetAttribute(mmaGemmK<1>, cudaFuncAttributeMaxDynamicSharedMemorySize, SMZ);

    detectMaskK<<<1, 256>>>(mask);
    convMaskK<<<64, 256>>>(mask);
    copyXinK<<<(NN * 32 + 255) / 256, 256>>>(xin, XYa);

    // layer 1: adj @ x_in -> XYa[:,128:256]; [x_in|adj@x_in] @ W1 -> relu -> XR
    mmaGemmK<0><<<128, 512, SMZ>>>(adj, NN, xin, 128, XYa + 128, 256, NN, nullptr);
    mmaGemmK<1><<<128, 512, SMZ>>>(XYa, 256, W1, 128, XR, 128, 256, b1);
    statsK<<<128, 128>>>(XR, part);
    bn1K<<<128, 128>>>(XR, part, g1, be1, XYb, out, out_size);

    // layer 2: adj @ x1 -> XYb[:,128:256]; [x1|adj@x1] @ W2 -> relu -> XR
    mmaGemmK<0><<<128, 512, SMZ>>>(adj, NN, XYb, 256, XYb + 128, 256, NN, nullptr);
    mmaGemmK<1><<<128, 512, SMZ>>>(XYb, 256, W2, 128, XR, 128, 256, b2);
    statsK<<<128, 128>>>(XR, part);
    bn2K<<<128, 128>>>(XR, part, g2, be2);

    // outputs
    segOutK<<<GG, 128>>>(xin, XYb, XR, idx, W4, b4, out, out_size);
    ovrK<<<NN / 8, 256>>>(pos);
    seedK<<<1, 32>>>(seed, nseed);
    amax1K<<<NN / 256, 256>>>();
    amax2K<<<1, 64>>>(out, out_size);
}

// round 14
// speedup vs baseline: 1.2596x; 1.2596x over previous
#include <cuda_runtime.h>
#include <cstdint>
#include <cstddef>

#define NN 16384
#define GG 64

// ------------------------- device scratch (static) -------------------------
__device__ float  g_XYa[NN * 256];   // [x_in | adj@x_in], ld 256
__device__ float  g_XYb[NN * 256];   // [x1   | adj@x1  ], ld 256
__device__ float  g_XR [NN * 128];   // relu(FC) output, reused per layer
__device__ double g_part[128 * 256];
__device__ float  g_inf[NN];
__device__ float  g_ovr[NN];
__device__ unsigned char g_mask[NN];
__device__ int    g_maskMode;
__device__ float  g_bv[64];
__device__ int    g_bi[64];

// ------------------------- helpers -------------------------
__device__ __forceinline__ float tf32r(float v) {
    uint32_t r; asm("cvt.rna.tf32.f32 %0, %1;" : "=r"(r) : "f"(v));
    return __uint_as_float(r);
}
__device__ __forceinline__ void mma8(float c[4],
                                     uint32_t a0, uint32_t a1, uint32_t a2, uint32_t a3,
                                     uint32_t b0, uint32_t b1) {
    asm volatile(
        "mma.sync.aligned.m16n8k8.row.col.f32.tf32.tf32.f32 "
        "{%0,%1,%2,%3},{%4,%5,%6,%7},{%8,%9},{%0,%1,%2,%3};"
        : "+f"(c[0]), "+f"(c[1]), "+f"(c[2]), "+f"(c[3])
        : "r"(a0), "r"(a1), "r"(a2), "r"(a3), "r"(b0), "r"(b1));
}

// ------------------------- mask dtype detection -------------------------
__global__ void detectMaskK(const void* m) {
    const int*   mi = (const int*)m;
    const float* mf = (const float*)m;
    __shared__ int bad_i32, bad_f32, one_i32, one_f32;
    if (threadIdx.x == 0) { bad_i32 = 0; bad_f32 = 0; one_i32 = 0; one_f32 = 0; }
    __syncthreads();
    for (int i = threadIdx.x; i < 4096; i += blockDim.x) {
        int v = mi[i];
        if (v != 0 && v != 1) atomicOr(&bad_i32, 1);
        if (v == 1) atomicOr(&one_i32, 1);
        float f = mf[i];
        if (!(f == 0.0f || f == 1.0f)) atomicOr(&bad_f32, 1);
        if (f == 1.0f) atomicOr(&one_f32, 1);
    }
    __syncthreads();
    if (threadIdx.x == 0) {
        int mode;
        if (!bad_i32 && one_i32) mode = 0;
        else if (!bad_f32 && one_f32) mode = 1;
        else mode = 2;
        g_maskMode = mode;
    }
}

__global__ void convMaskK(const void* m) {
    int i = blockIdx.x * blockDim.x + threadIdx.x;
    if (i >= NN) return;
    int mode = g_maskMode;
    bool b;
    if (mode == 0)      b = ((const int*)m)[i] != 0;
    else if (mode == 1) b = ((const float*)m)[i] != 0.0f;
    else                b = ((const unsigned char*)m)[i] != 0;
    g_mask[i] = b ? 1 : 0;
}

// ------------------------- copy x_in into XYa[:,0:128] -------------------------
__global__ void copyXinK(const float* __restrict__ xin, float* __restrict__ XYa) {
    int i = blockIdx.x * blockDim.x + threadIdx.x;
    if (i >= NN * 32) return;
    int row = i >> 5, q = i & 31;
    ((float4*)XYa)[(size_t)row * 64 + q] = ((const float4*)xin)[i];
}

// ------------------------- tf32x3 mma.sync GEMM (round-9 proven config) --------------
// C[M x 128] = A[M x K] @ B[K x 128], fp32 in/out, tf32 3-product emulation.
// CTA: 128m x 128n tile, BK=32, 512 threads (16 warps, each 32m x 32n).
// fp32 stored once in smem; hi = cvt.rna.tf32 in registers; lo = v - hi RAW.
// Smem: 2 stages x (As[128][40] + Bs[128][40]) = 81920 B dynamic.
template <int MODE>
__global__ void __launch_bounds__(512, 1) mmaGemmK(
    const float* __restrict__ A, int lda,
    const float* __restrict__ B, int ldb,
    float* __restrict__ C, int ldc,
    int K, const float* __restrict__ bias)
{
    extern __shared__ float sm[];   // [2][10240]: As 5120 + Bs 5120 per stage

    const int t    = threadIdx.x;
    const int lane = t & 31;
    const int w    = t >> 5;
    const int mg   = w & 3;
    const int ng   = w >> 2;
    const int quad = lane >> 2;
    const int tid4 = lane & 3;
    const int m0   = blockIdx.x * 128;

    const int ar  = t >> 2;
    const int akb = (t & 3) * 8;
    const int bkr = t & 31;
    const int bnb = (t >> 5) * 8;

    const float* Ag = A + (size_t)(m0 + ar) * lda + akb;
    const float* Bg = B + (size_t)bkr * ldb + bnb;

    const int bcol = ((bkr >> 3) << 3) | (((bkr & 3) << 1) | ((bkr & 7) >> 2));

    float acc[2][4][4];
#pragma unroll
    for (int i = 0; i < 2; ++i)
#pragma unroll
        for (int j = 0; j < 4; ++j)
#pragma unroll
            for (int e = 0; e < 4; ++e) acc[i][j][e] = 0.0f;

    float4 apre[2], bpre[2];
#define LDGS(K0) do { \
        apre[0] = *(const float4*)(Ag + (K0)); \
        apre[1] = *(const float4*)(Ag + (K0) + 4); \
        bpre[0] = *(const float4*)(Bg + (size_t)(K0) * ldb); \
        bpre[1] = *(const float4*)(Bg + (size_t)(K0) * ldb + 4); \
    } while (0)

#define STST(BUF) do { \
        float* Asd = sm + (BUF) * 10240; \
        float* Bsd = Asd + 5120; \
        float4 u = apre[0], v = apre[1]; \
        float4 p0 = {u.x, v.x, u.y, v.y}; \
        float4 p1 = {u.z, v.z, u.w, v.w}; \
        *(float4*)(Asd + ar * 40 + akb)     = p0; \
        *(float4*)(Asd + ar * 40 + akb + 4) = p1; \
        _Pragma("unroll") \
        for (int jj = 0; jj < 2; ++jj) { \
            float4 bv = bpre[jj]; \
            Bsd[(bnb + jj * 4 + 0) * 40 + bcol] = bv.x; \
            Bsd[(bnb + jj * 4 + 1) * 40 + bcol] = bv.y; \
            Bsd[(bnb + jj * 4 + 2) * 40 + bcol] = bv.z; \
            Bsd[(bnb + jj * 4 + 3) * 40 + bcol] = bv.w; \
        } \
    } while (0)

    LDGS(0);
    STST(0);
    __syncthreads();

    const int nT = K >> 5;
    for (int kt = 0; kt < nT; ++kt) {
        const int cur = kt & 1;
        const float* Asc = sm + cur * 10240;
        const float* Bsc = Asc + 5120;

        if (kt + 1 < nT) LDGS((kt + 1) << 5);

#pragma unroll
        for (int kk8 = 0; kk8 < 4; ++kk8) {
            const int kp = kk8 * 8 + 2 * tid4;
            uint32_t ah[2][4], al[2][4];
#pragma unroll
            for (int i = 0; i < 2; ++i) {
                int row0 = mg * 32 + i * 16 + quad;
                float2 p = *(const float2*)(Asc + row0 * 40 + kp);
                float2 q = *(const float2*)(Asc + (row0 + 8) * 40 + kp);
                float h0 = tf32r(p.x), h1 = tf32r(q.x), h2 = tf32r(p.y), h3 = tf32r(q.y);
                ah[i][0] = __float_as_uint(h0);
                ah[i][1] = __float_as_uint(h1);
                ah[i][2] = __float_as_uint(h2);
                ah[i][3] = __float_as_uint(h3);
                al[i][0] = __float_as_uint(p.x - h0);
                al[i][1] = __float_as_uint(q.x - h1);
                al[i][2] = __float_as_uint(p.y - h2);
                al[i][3] = __float_as_uint(q.y - h3);
            }
#pragma unroll
            for (int j = 0; j < 4; ++j) {
                int n = ng * 32 + j * 8 + quad;
                float2 b = *(const float2*)(Bsc + n * 40 + kp);
                float bh0f = tf32r(b.x), bh1f = tf32r(b.y);
                uint32_t bh0 = __float_as_uint(bh0f);
                uint32_t bh1 = __float_as_uint(bh1f);
                uint32_t bl0 = __float_as_uint(b.x - bh0f);
                uint32_t bl1 = __float_as_uint(b.y - bh1f);
#pragma unroll
                for (int i = 0; i < 2; ++i) {
                    mma8(acc[i][j], ah[i][0], ah[i][1], ah[i][2], ah[i][3], bh0, bh1);
                    mma8(acc[i][j], ah[i][0], ah[i][1], ah[i][2], ah[i][3], bl0, bl1);
                    mma8(acc[i][j], al[i][0], al[i][1], al[i][2], al[i][3], bh0, bh1);
                }
            }
        }

        if (kt + 1 < nT) STST(cur ^ 1);
        __syncthreads();
    }
#undef LDGS
#undef STST

#pragma unroll
    for (int i = 0; i < 2; ++i) {
        int r0 = m0 + mg * 32 + i * 16 + quad;
#pragma unroll
        for (int j = 0; j < 4; ++j) {
            int c0 = ng * 32 + j * 8 + 2 * tid4;
            float v0 = acc[i][j][0], v1 = acc[i][j][1];
            float v2 = acc[i][j][2], v3 = acc[i][j][3];
            if (MODE == 1) {
                float bb0 = bias[c0], bb1 = bias[c0 + 1];
                v0 = fmaxf(v0 + bb0, 0.0f); v1 = fmaxf(v1 + bb1, 0.0f);
                v2 = fmaxf(v2 + bb0, 0.0f); v3 = fmaxf(v3 + bb1, 0.0f);
            }
            float2 p0 = {v0, v1}, p1 = {v2, v3};
            *(float2*)(C + (size_t)r0 * ldc + c0)       = p0;
            *(float2*)(C + (size_t)(r0 + 8) * ldc + c0) = p1;
        }
    }
}

// ------------------------- column stats (deterministic partials) -------------------------
__global__ void statsK(const float* __restrict__ X, double* __restrict__ part) {
    int c  = threadIdx.x;
    int r0 = blockIdx.x * 128;
    double s = 0.0, q = 0.0;
    for (int r = 0; r < 128; ++r) {
        double v = (double)X[(size_t)(r0 + r) * 128 + c];
        s += v; q += v * v;
    }
    part[blockIdx.x * 256 + c]       = s;
    part[blockIdx.x * 256 + 128 + c] = q;
}

// ------------------------- BN1 + mask -> x1, h1 -> infset -------------------------
__global__ void bn1K(const float* __restrict__ XR, const double* __restrict__ part,
                     const float* __restrict__ g, const float* __restrict__ be,
                     float* __restrict__ X1, float* __restrict__ dout, int out_size) {
    __shared__ float scale[128], shift[128];
    int c = threadIdx.x;
    double s = 0.0, q = 0.0;
    for (int b = 0; b < 128; ++b) { s += part[b * 256 + c]; q += part[b * 256 + 128 + c]; }
    double mu  = s * (1.0 / 16384.0);
    double var = q * (1.0 / 16384.0) - mu * mu; if (var < 0.0) var = 0.0;
    float sc = g[c] * (float)(1.0 / sqrt(var + 1e-5));
    scale[c] = sc;
    shift[c] = be[c] - (float)mu * sc;
    __syncthreads();

    int row = blockIdx.x * 128 + c;
    float sel = g_mask[row] ? 0.0f : 1.0f;
    const float4* xr = (const float4*)(XR + (size_t)row * 128);
    float4* x1 = (float4*)(X1 + (size_t)row * 256);
    float h = 0.0f;
    for (int qd = 0; qd < 32; ++qd) {
        float4 v = xr[qd];
        float4 rr;
        rr.x = sel * (v.x * scale[4 * qd + 0] + shift[4 * qd + 0]);
        rr.y = sel * (v.y * scale[4 * qd + 1] + shift[4 * qd + 1]);
        rr.z = sel * (v.z * scale[4 * qd + 2] + shift[4 * qd + 2]);
        rr.w = sel * (v.w * scale[4 * qd + 3] + shift[4 * qd + 3]);
        h += rr.x + rr.y + rr.z + rr.w;
        x1[qd] = rr;
    }
    float inf = (h <= 0.0f) ? 1.0f : 0.0f;
    g_inf[row] = inf;
    if (64 + row < out_size) dout[64 + row] = inf;
}

// ------------------------- BN2 + mask -> x2 (in place) -------------------------
__global__ void bn2K(float* __restrict__ XR, const double* __restrict__ part,
                     const float* __restrict__ g, const float* __restrict__ be) {
    __shared__ float scale[128], shift[128];
    int c = threadIdx.x;
    double s = 0.0, q = 0.0;
    for (int b = 0; b < 128; ++b) { s += part[b * 256 + c]; q += part[b * 256 + 128 + c]; }
    double mu  = s * (1.0 / 16384.0);
    double var = q * (1.0 / 16384.0) - mu * mu; if (var < 0.0) var = 0.0;
    float sc = g[c] * (float)(1.0 / sqrt(var + 1e-5));
    scale[c] = sc;
    shift[c] = be[c] - (float)mu * sc;
    __syncthreads();

    int row = blockIdx.x * 128 + c;
    float sel = g_mask[row] ? 0.0f : 1.0f;
    float4* xr = (float4*)(XR + (size_t)row * 128);
    for (int qd = 0; qd < 32; ++qd) {
        float4 v = xr[qd];
        float4 rr;
        rr.x = sel * (v.x * scale[4 * qd + 0] + shift[4 * qd + 0]);
        rr.y = sel * (v.y * scale[4 * qd + 1] + shift[4 * qd + 1]);
        rr.z = sel * (v.z * scale[4 * qd + 2] + shift[4 * qd + 2]);
        rr.w = sel * (v.w * scale[4 * qd + 3] + shift[4 * qd + 3]);
        xr[qd] = rr;
    }
}

// ------------------------- per-segment sum + final FC -------------------------
__device__ __forceinline__ int lowerBound(const int* a, int n, int key) {
    int lo = 0, hi = n;
    while (lo < hi) { int mid = (lo + hi) >> 1; if (a[mid] < key) lo = mid + 1; else hi = mid; }
    return lo;
}

__global__ void segOutK(const float* __restrict__ xin, const float* __restrict__ x1,
                        const float* __restrict__ x2, const int* __restrict__ idx,
                        const float* __restrict__ W4, const float* __restrict__ b4,
                        float* __restrict__ dout, int out_size) {
    int g = blockIdx.x, t = threadIdx.x;
    __shared__ float wgt[384];
    __shared__ float red[128];
    wgt[t] = W4[t]; wgt[128 + t] = W4[128 + t]; wgt[256 + t] = W4[256 + t];
    __syncthreads();
    int lo = lowerBound(idx, NN, g);
    int hi = lowerBound(idx, NN, g + 1);
    float acc = 0.0f;
    for (int r = lo; r < hi; ++r) {
        acc += xin[(size_t)r * 128 + t] * wgt[t]
             + x1 [(size_t)r * 256 + t] * wgt[128 + t]
             + x2 [(size_t)r * 128 + t] * wgt[256 + t];
    }
    red[t] = acc;
    __syncthreads();
    for (int s2 = 64; s2 > 0; s2 >>= 1) {
        if (t < s2) red[t] += red[t + s2];
        __syncthreads();
    }
    if (t == 0 && g < out_size) dout[g] = fmaxf(red[0] + b4[0], 0.0f);
}

// ------------------------- ovr = pos @ infset -------------------------
__global__ void ovrK(const float* __restrict__ pos) {
    int row  = blockIdx.x * 8 + (threadIdx.x >> 5);
    int lane = threadIdx.x & 31;
    const float4* p = (const float4*)(pos + (size_t)row * NN);
    const float4* f = (const float4*)g_inf;
    float a = 0.0f;
    for (int j = lane; j < NN / 4; j += 32) {
        float4 pv = p[j]; float4 iv = f[j];
        a += pv.x * iv.x + pv.y * iv.y + pv.z * iv.z + pv.w * iv.w;
    }
#pragma unroll
    for (int o = 16; o > 0; o >>= 1) a += __shfl_down_sync(0xffffffffu, a, o);
    if (lane == 0) g_ovr[row] = a;
}

__global__ void seedK(const int* __restrict__ seed, int nseed) {
    int t = threadIdx.x;
    if (t < nseed) {
        int s = seed[t];
        if (s >= 0 && s < NN) g_ovr[s] = __int_as_float(0xff800000);
    }
}

// ------------------------- argmax -------------------------
__global__ void amax1K() {
    __shared__ float sv[256]; __shared__ int si[256];
    int t = threadIdx.x;
    int i = blockIdx.x * 256 + t;
    sv[t] = g_ovr[i]; si[t] = i;
    __syncthreads();
    for (int s = 128; s > 0; s >>= 1) {
        if (t < s) {
            if (sv[t + s] > sv[t] || (sv[t + s] == sv[t] && si[t + s] < si[t])) {
                sv[t] = sv[t + s]; si[t] = si[t + s];
            }
        }
        __syncthreads();
    }
    if (t == 0) { g_bv[blockIdx.x] = sv[0]; g_bi[blockIdx.x] = si[0]; }
}

__global__ void amax2K(float* __restrict__ dout, int out_size) {
    __shared__ float sv[64]; __shared__ int si[64];
    int t = threadIdx.x;
    sv[t] = g_bv[t]; si[t] = g_bi[t];
    __syncthreads();
    for (int s = 32; s > 0; s >>= 1) {
        if (t < s) {
            if (sv[t + s] > sv[t] || (sv[t + s] == sv[t] && si[t + s] < si[t])) {
                sv[t] = sv[t + s]; si[t] = si[t + s];
            }
        }
        __syncthreads();
    }
    if (t == 0) {
        if (64 + NN < out_size) dout[64 + NN] = (float)si[0];
    }
}

// ------------------------- launch -------------------------
extern "C" void kernel_launch(void* const* d_in, const int* in_sizes, int n_in,
                              void* d_out, int out_size) {
    const float* adj  = (const float*)d_in[0];
    const float* xin  = (const float*)d_in[1];
    const void*  mask =               d_in[2];
    const float* pos  = (const float*)d_in[3];
    const int*   idx  = (const int*)  d_in[4];
    const int*   seed = (const int*)  d_in[5];
    const float* W1  = (const float*)d_in[7];
    const float* b1  = (const float*)d_in[8];
    const float* W2  = (const float*)d_in[9];
    const float* b2  = (const float*)d_in[10];
    const float* W4  = (const float*)d_in[11];
    const float* b4  = (const float*)d_in[12];
    const float* g1  = (const float*)d_in[13];
    const float* be1 = (const float*)d_in[14];
    const float* g2  = (const float*)d_in[15];
    const float* be2 = (const float*)d_in[16];
    float* out = (float*)d_out;
    int nseed = in_sizes[5];

    float  *XYa, *XYb, *XR;
    double *part;
    cudaGetSymbolAddress((void**)&XYa,  g_XYa);
    cudaGetSymbolAddress((void**)&XYb,  g_XYb);
    cudaGetSymbolAddress((void**)&XR,   g_XR);
    cudaGetSymbolAddress((void**)&part, g_part);

    // side stream + fork/join events, created once on the first (uncaptured) call
    static cudaStream_t sSide = nullptr;
    static cudaEvent_t  eFork = nullptr, eJoin = nullptr;
    if (sSide == nullptr) {
        cudaStreamCreateWithFlags(&sSide, cudaStreamNonBlocking);
        cudaEventCreateWithFlags(&eFork, cudaEventDisableTiming);
        cudaEventCreateWithFlags(&eJoin, cudaEventDisableTiming);
    }

    const int SMZ = 2 * 10240 * 4;  // 81920 B dynamic smem
    cudaFuncSetAttribute(mmaGemmK<0>, cudaFuncAttributeMaxDynamicSharedMemorySize, SMZ);
    cudaFuncSetAttribute(mmaGemmK<1>, cudaFuncAttributeMaxDynamicSharedMemorySize, SMZ);

    detectMaskK<<<1, 256>>>(mask);
    convMaskK<<<64, 256>>>(mask);
    copyXinK<<<(NN * 32 + 255) / 256, 256>>>(xin, XYa);

    // layer 1: adj @ x_in -> XYa[:,128:256]; [x_in|adj@x_in] @ W1 -> relu -> XR
    mmaGemmK<0><<<128, 512, SMZ>>>(adj, NN, xin, 128, XYa + 128, 256, NN, nullptr);
    mmaGemmK<1><<<128, 512, SMZ>>>(XYa, 256, W1, 128, XR, 128, 256, b1);
    statsK<<<128, 128>>>(XR, part);
    bn1K<<<128, 128>>>(XR, part, g1, be1, XYb, out, out_size);

    // ---- fork: influence-spread branch depends only on g_inf (bn1K) ----
    cudaEventRecord(eFork, 0);
    cudaStreamWaitEvent(sSide, eFork, 0);
    ovrK<<<NN / 8, 256, 0, sSide>>>(pos);
    seedK<<<1, 32, 0, sSide>>>(seed, nseed);
    amax1K<<<NN / 256, 256, 0, sSide>>>();
    amax2K<<<1, 64, 0, sSide>>>(out, out_size);
    cudaEventRecord(eJoin, sSide);

    // ---- main: layer 2 runs concurrently with the side branch ----
    mmaGemmK<0><<<128, 512, SMZ>>>(adj, NN, XYb, 256, XYb + 128, 256, NN, nullptr);
    mmaGemmK<1><<<128, 512, SMZ>>>(XYb, 256, W2, 128, XR, 128, 256, b2);
    statsK<<<128, 128>>>(XR, part);
    bn2K<<<128, 128>>>(XR, part, g2, be2);
    segOutK<<<GG, 128>>>(xin, XYb, XR, idx, W4, b4, out, out_size);

    // ---- join ----
    cudaStreamWaitEvent(0, eJoin, 0);
}